// round 2
// baseline (speedup 1.0000x reference)
#include <cuda_runtime.h>
#include <math.h>

#define NLEV 16
#define TMASK ((1u << 19) - 1u)
#define PR1 2654435761u
#define PR2 805459861u
#define PR3 3674653429u
#define TPB 128

// shared memory layout (floats)
#define SW2_OFF (5 * 4096)
#define SF_OFF  (5 * 4096 + 64)
#define SMEM_FLOATS (5 * 4096 + 64 + 64 * TPB)   // 28736 floats = 114944 B

struct ResParams { int r[NLEV]; };

// ---------------- packed fp32x2 helpers (Blackwell 2x fp32 path) ----------------
__device__ __forceinline__ unsigned long long pk2(float a, float b) {
    unsigned long long r;
    asm("mov.b64 %0, {%1, %2};" : "=l"(r) : "f"(a), "f"(b));
    return r;
}
__device__ __forceinline__ void upk2(unsigned long long v, float& a, float& b) {
    asm("mov.b64 {%0, %1}, %2;" : "=f"(a), "=f"(b) : "l"(v));
}
__device__ __forceinline__ void ffma2(unsigned long long& d, unsigned long long a, unsigned long long b) {
    asm("fma.rn.f32x2 %0, %1, %2, %0;" : "+l"(d) : "l"(a), "l"(b));
}

// ---------------- mat-vec: input from smem column (stride TPB) ----------------
__device__ __forceinline__ void mv_smem(const float* __restrict__ W, const float* __restrict__ fc,
                                        unsigned long long acc[32]) {
#pragma unroll
    for (int q = 0; q < 32; q++) acc[q] = 0ull;
#pragma unroll 4
    for (int k = 0; k < 64; k++) {
        float f = fc[k * TPB];
        unsigned long long f2 = pk2(f, f);
        const ulonglong2* wr = (const ulonglong2*)(W + (k << 6));
#pragma unroll
        for (int q = 0; q < 16; q++) {
            ulonglong2 w = wr[q];
            ffma2(acc[2 * q],     f2, w.x);
            ffma2(acc[2 * q + 1], f2, w.y);
        }
    }
}

// ---------------- mat-vec: input from packed registers ----------------
__device__ __forceinline__ void mv_regs(const float* __restrict__ W, const unsigned long long in[32],
                                        unsigned long long acc[32]) {
#pragma unroll
    for (int q = 0; q < 32; q++) acc[q] = 0ull;
#pragma unroll 2
    for (int kp = 0; kp < 32; kp++) {
        float fa, fb;
        upk2(in[kp], fa, fb);
        unsigned long long f2a = pk2(fa, fa);
        unsigned long long f2b = pk2(fb, fb);
        const ulonglong2* w0 = (const ulonglong2*)(W + (kp << 7));
        const ulonglong2* w1 = (const ulonglong2*)(W + (kp << 7) + 64);
#pragma unroll
        for (int q = 0; q < 16; q++) {
            ulonglong2 wa = w0[q];
            ffma2(acc[2 * q],     f2a, wa.x);
            ffma2(acc[2 * q + 1], f2a, wa.y);
        }
#pragma unroll
        for (int q = 0; q < 16; q++) {
            ulonglong2 wb = w1[q];
            ffma2(acc[2 * q],     f2b, wb.x);
            ffma2(acc[2 * q + 1], f2b, wb.y);
        }
    }
}

// ---------------- 3D hash-grid level encode ----------------
__device__ __forceinline__ void enc3(const float2* __restrict__ tb, float x0, float x1, float x2,
                                     int R, float& o0, float& o1) {
    float fr = (float)R;
    float p0 = x0 * fr, p1 = x1 * fr, p2 = x2 * fr;
    float g0 = floorf(p0), g1 = floorf(p1), g2 = floorf(p2);
    float f0 = p0 - g0, f1 = p1 - g1, f2 = p2 - g2;
    unsigned i0 = (unsigned)(int)g0, i1 = (unsigned)(int)g1, i2 = (unsigned)(int)g2;
    unsigned hx[2] = { i0, i0 + 1u };
    unsigned hy[2] = { i1 * PR1, (i1 + 1u) * PR1 };
    unsigned hz[2] = { i2 * PR2, (i2 + 1u) * PR2 };
    float wx[2] = { 1.f - f0, f0 };
    float wy[2] = { 1.f - f1, f1 };
    float wz[2] = { 1.f - f2, f2 };
    float2 v[8];
#pragma unroll
    for (int c = 0; c < 8; c++) {
        unsigned h = (hx[(c >> 2) & 1] ^ hy[(c >> 1) & 1] ^ hz[c & 1]) & TMASK;
        v[c] = __ldg(tb + h);
    }
    float a0 = 0.f, a1 = 0.f;
#pragma unroll
    for (int c = 0; c < 8; c++) {
        float w = wx[(c >> 2) & 1] * wy[(c >> 1) & 1];
        w *= wz[c & 1];
        a0 = fmaf(w, v[c].x, a0);
        a1 = fmaf(w, v[c].y, a1);
    }
    o0 = a0; o1 = a1;
}

// ---------------- 4D hash-grid level encode ----------------
__device__ __forceinline__ void enc4(const float2* __restrict__ tb, float x0, float x1, float x2, float x3,
                                     int R, float& o0, float& o1) {
    float fr = (float)R;
    float p0 = x0 * fr, p1 = x1 * fr, p2 = x2 * fr, p3 = x3 * fr;
    float g0 = floorf(p0), g1 = floorf(p1), g2 = floorf(p2), g3 = floorf(p3);
    float f0 = p0 - g0, f1 = p1 - g1, f2 = p2 - g2, f3 = p3 - g3;
    unsigned i0 = (unsigned)(int)g0, i1 = (unsigned)(int)g1;
    unsigned i2 = (unsigned)(int)g2, i3 = (unsigned)(int)g3;
    unsigned hx[2] = { i0, i0 + 1u };
    unsigned hy[2] = { i1 * PR1, (i1 + 1u) * PR1 };
    unsigned hz[2] = { i2 * PR2, (i2 + 1u) * PR2 };
    unsigned hw[2] = { i3 * PR3, (i3 + 1u) * PR3 };
    float wx[2] = { 1.f - f0, f0 };
    float wy[2] = { 1.f - f1, f1 };
    float wz[2] = { 1.f - f2, f2 };
    float ww[2] = { 1.f - f3, f3 };
    float2 v[16];
#pragma unroll
    for (int c = 0; c < 16; c++) {
        unsigned h = (hx[(c >> 3) & 1] ^ hy[(c >> 2) & 1] ^ hz[(c >> 1) & 1] ^ hw[c & 1]) & TMASK;
        v[c] = __ldg(tb + h);
    }
    float a0 = 0.f, a1 = 0.f;
#pragma unroll
    for (int c = 0; c < 16; c++) {
        float w = wx[(c >> 3) & 1] * wy[(c >> 2) & 1];
        w *= wz[(c >> 1) & 1];
        w *= ww[c & 1];
        a0 = fmaf(w, v[c].x, a0);
        a1 = fmaf(w, v[c].y, a1);
    }
    o0 = a0; o1 = a1;
}

__global__ void __launch_bounds__(TPB, 2)
fused_hash_mlp_kernel(const float* __restrict__ x,
                      const float* __restrict__ tptr,
                      const float* __restrict__ tbl_s,
                      const float* __restrict__ tbl_d,
                      const float* __restrict__ w10, const float* __restrict__ w11,
                      const float* __restrict__ w12, const float* __restrict__ w20,
                      const float* __restrict__ w21, const float* __restrict__ w22,
                      const float* __restrict__ alphap,
                      float* __restrict__ out, int N, ResParams rp) {
    extern __shared__ float sm[];
    const int tid = threadIdx.x;

    // ---- cooperative weight staging into smem ----
    {
        const float* srcs[5] = { w10, w11, w12, w20, w21 };
#pragma unroll
        for (int m = 0; m < 5; m++) {
            const float4* s4 = (const float4*)srcs[m];
            float4* d4 = (float4*)(sm + m * 4096);
#pragma unroll
            for (int u = 0; u < 8; u++) d4[tid + u * TPB] = s4[tid + u * TPB];
        }
        if (tid < 16) ((float4*)(sm + SW2_OFF))[tid] = ((const float4*)w22)[tid];
    }
    __syncthreads();

    const int i = blockIdx.x * TPB + tid;
    if (i >= N) return;

    const float x0 = x[3 * i], x1 = x[3 * i + 1], x2 = x[3 * i + 2];
    const float tv = __ldg(tptr);
    float* fc = sm + SF_OFF + tid;   // this thread's private smem column, stride TPB

    // ---- hash encodings: static 3D (feat[0:32]), dynamic 4D (feat[32:64]) ----
#pragma unroll 1
    for (int l = 0; l < NLEV; l++) {
        float a0, a1;
        enc3((const float2*)tbl_s + ((size_t)l << 19), x0, x1, x2, rp.r[l], a0, a1);
        fc[(2 * l) * TPB]     = a0;
        fc[(2 * l + 1) * TPB] = a1;
    }
#pragma unroll 1
    for (int l = 0; l < NLEV; l++) {
        float a0, a1;
        enc4((const float2*)tbl_d + ((size_t)l << 19), x0, x1, x2, tv, rp.r[l], a0, a1);
        fc[(32 + 2 * l) * TPB]     = a0;
        fc[(32 + 2 * l + 1) * TPB] = a1;
    }

    const float alpha = __ldg(alphap);
    const float beta = 1.f - alpha;

    unsigned long long h[32], acc[32];

    // net_1 layer 0: feat (smem) -> h
    mv_smem(sm, fc, acc);
#pragma unroll
    for (int q = 0; q < 32; q++) {
        float a, b; upk2(acc[q], a, b);
        h[q] = pk2(fmaxf(a, 0.f), fmaxf(b, 0.f));
    }
    // net_1 layer 1
    mv_regs(sm + 4096, h, acc);
#pragma unroll
    for (int q = 0; q < 32; q++) {
        float a, b; upk2(acc[q], a, b);
        h[q] = pk2(fmaxf(a, 0.f), fmaxf(b, 0.f));
    }
    // net_1 layer 2 + adaptive skip blend
    mv_regs(sm + 8192, h, acc);
#pragma unroll
    for (int q = 0; q < 32; q++) {
        float a, b; upk2(acc[q], a, b);
        a = fmaxf(a, 0.f) * alpha + beta * fc[(2 * q) * TPB];
        b = fmaxf(b, 0.f) * alpha + beta * fc[(2 * q + 1) * TPB];
        h[q] = pk2(a, b);
    }
    // net_2 layer 0
    mv_regs(sm + 12288, h, acc);
#pragma unroll
    for (int q = 0; q < 32; q++) {
        float a, b; upk2(acc[q], a, b);
        h[q] = pk2(fmaxf(a, 0.f), fmaxf(b, 0.f));
    }
    // net_2 layer 1
    mv_regs(sm + 16384, h, acc);
#pragma unroll
    for (int q = 0; q < 32; q++) {
        float a, b; upk2(acc[q], a, b);
        h[q] = pk2(fmaxf(a, 0.f), fmaxf(b, 0.f));
    }
    // final linear layer -> scalar
    float s = 0.f;
    const float* w2l = sm + SW2_OFF;
#pragma unroll
    for (int q = 0; q < 32; q++) {
        float a, b; upk2(h[q], a, b);
        s = fmaf(a, w2l[2 * q], s);
        s = fmaf(b, w2l[2 * q + 1], s);
    }
    out[i] = s;
}

extern "C" void kernel_launch(void* const* d_in, const int* in_sizes, int n_in,
                              void* d_out, int out_size) {
    (void)in_sizes; (void)n_in;
    const float* x      = (const float*)d_in[0];
    const float* t      = (const float*)d_in[1];
    const float* tbl_s  = (const float*)d_in[2];
    const float* tbl_d  = (const float*)d_in[3];
    const float* w10    = (const float*)d_in[4];
    const float* w11    = (const float*)d_in[5];
    const float* w12    = (const float*)d_in[6];
    const float* w20    = (const float*)d_in[7];
    const float* w21    = (const float*)d_in[8];
    const float* w22    = (const float*)d_in[9];
    const float* alpha  = (const float*)d_in[10];
    float* out = (float*)d_out;

    const int N = out_size;
    if (N <= 0) return;

    // RES[l] = floor(16 * b^l), b = (2048/16)^(1/15) — identical double-precision
    // expressions as the Python reference (same libm pow → bit-identical floors).
    ResParams rp;
    double b = pow(2048.0 / 16.0, 1.0 / 15.0);
    for (int l = 0; l < NLEV; l++)
        rp.r[l] = (int)floor(16.0 * pow(b, (double)l));

    size_t smem = SMEM_FLOATS * sizeof(float);
    cudaFuncSetAttribute(fused_hash_mlp_kernel,
                         cudaFuncAttributeMaxDynamicSharedMemorySize, (int)smem);

    int blocks = (N + TPB - 1) / TPB;
    fused_hash_mlp_kernel<<<blocks, TPB, smem>>>(
        x, t, tbl_s, tbl_d, w10, w11, w12, w20, w21, w22, alpha, out, N, rp);
}

// round 4
// speedup vs baseline: 2.4220x; 2.4220x over previous
#include <cuda_runtime.h>
#include <cuda_bf16.h>
#include <math.h>
#include <stdint.h>

#define NLEV 16
#define TMASK ((1u << 19) - 1u)
#define PR1 2654435761u
#define PR2 805459861u
#define PR3 3674653429u
#define TPB 384
#define NWARP 12

// ---------------- smem layout (bytes) ----------------
// Weight fragments: 5 layers x [hi 8KB | lo 8KB]; tile (kt*8+nt)*256 + lane*8 + j*4
#define WFRAG_OFF 0
#define W22_OFF   81920                  // 64 floats
#define FEAT_OFF  82176                  // 384 rows x 272B ([hi 128B][lo 128B][pad 16B])
#define FEAT_STRIDE 272
#define SMEM_TOTAL (82176 + TPB * FEAT_STRIDE)   // 186624 B

struct ResParams { int r[NLEV]; };

// ---------------- helpers ----------------
__device__ __forceinline__ void mma16816(float d[4], const uint32_t a[4], uint32_t b0, uint32_t b1) {
    asm volatile("mma.sync.aligned.m16n8k16.row.col.f32.bf16.bf16.f32 "
        "{%0,%1,%2,%3}, {%4,%5,%6,%7}, {%8,%9}, {%0,%1,%2,%3};"
        : "+f"(d[0]), "+f"(d[1]), "+f"(d[2]), "+f"(d[3])
        : "r"(a[0]), "r"(a[1]), "r"(a[2]), "r"(a[3]), "r"(b0), "r"(b1));
}

__device__ __forceinline__ void split2(float v0, float v1, uint32_t& hi, uint32_t& lo) {
    __nv_bfloat162 h, l;
    h.x = __float2bfloat16_rn(v0);
    h.y = __float2bfloat16_rn(v1);
    l.x = __float2bfloat16_rn(v0 - __bfloat162float(h.x));
    l.y = __float2bfloat16_rn(v1 - __bfloat162float(h.y));
    hi = *reinterpret_cast<uint32_t*>(&h);
    lo = *reinterpret_cast<uint32_t*>(&l);
}

// ---------------- hash-grid level encoders (fp32, identical math to ref) ----------------
__device__ __forceinline__ void enc3(const float2* __restrict__ tb, float x0, float x1, float x2,
                                     int R, float& o0, float& o1) {
    float fr = (float)R;
    float p0 = x0 * fr, p1 = x1 * fr, p2 = x2 * fr;
    float g0 = floorf(p0), g1 = floorf(p1), g2 = floorf(p2);
    float f0 = p0 - g0, f1 = p1 - g1, f2 = p2 - g2;
    unsigned i0 = (unsigned)(int)g0, i1 = (unsigned)(int)g1, i2 = (unsigned)(int)g2;
    unsigned hx[2] = { i0, i0 + 1u };
    unsigned hy[2] = { i1 * PR1, (i1 + 1u) * PR1 };
    unsigned hz[2] = { i2 * PR2, (i2 + 1u) * PR2 };
    float wx[2] = { 1.f - f0, f0 };
    float wy[2] = { 1.f - f1, f1 };
    float wz[2] = { 1.f - f2, f2 };
    float2 v[8];
#pragma unroll
    for (int c = 0; c < 8; c++) {
        unsigned h = (hx[(c >> 2) & 1] ^ hy[(c >> 1) & 1] ^ hz[c & 1]) & TMASK;
        v[c] = __ldg(tb + h);
    }
    float a0 = 0.f, a1 = 0.f;
#pragma unroll
    for (int c = 0; c < 8; c++) {
        float w = wx[(c >> 2) & 1] * wy[(c >> 1) & 1];
        w *= wz[c & 1];
        a0 = fmaf(w, v[c].x, a0);
        a1 = fmaf(w, v[c].y, a1);
    }
    o0 = a0; o1 = a1;
}

__device__ __forceinline__ void enc4(const float2* __restrict__ tb, float x0, float x1, float x2, float x3,
                                     int R, float& o0, float& o1) {
    float fr = (float)R;
    float p0 = x0 * fr, p1 = x1 * fr, p2 = x2 * fr, p3 = x3 * fr;
    float g0 = floorf(p0), g1 = floorf(p1), g2 = floorf(p2), g3 = floorf(p3);
    float f0 = p0 - g0, f1 = p1 - g1, f2 = p2 - g2, f3 = p3 - g3;
    unsigned i0 = (unsigned)(int)g0, i1 = (unsigned)(int)g1;
    unsigned i2 = (unsigned)(int)g2, i3 = (unsigned)(int)g3;
    unsigned hx[2] = { i0, i0 + 1u };
    unsigned hy[2] = { i1 * PR1, (i1 + 1u) * PR1 };
    unsigned hz[2] = { i2 * PR2, (i2 + 1u) * PR2 };
    unsigned hw[2] = { i3 * PR3, (i3 + 1u) * PR3 };
    float wx[2] = { 1.f - f0, f0 };
    float wy[2] = { 1.f - f1, f1 };
    float wz[2] = { 1.f - f2, f2 };
    float ww[2] = { 1.f - f3, f3 };
    float2 v[16];
#pragma unroll
    for (int c = 0; c < 16; c++) {
        unsigned h = (hx[(c >> 3) & 1] ^ hy[(c >> 2) & 1] ^ hz[(c >> 1) & 1] ^ hw[c & 1]) & TMASK;
        v[c] = __ldg(tb + h);
    }
    float a0 = 0.f, a1 = 0.f;
#pragma unroll
    for (int c = 0; c < 16; c++) {
        float w = wx[(c >> 3) & 1] * wy[(c >> 2) & 1];
        w *= wz[(c >> 1) & 1];
        w *= ww[c & 1];
        a0 = fmaf(w, v[c].x, a0);
        a1 = fmaf(w, v[c].y, a1);
    }
    o0 = a0; o1 = a1;
}

__global__ void __launch_bounds__(TPB, 1)
fused_hash_mlp_hmma(const float* __restrict__ x,
                    const float* __restrict__ tptr,
                    const float* __restrict__ tbl_s,
                    const float* __restrict__ tbl_d,
                    const float* __restrict__ w10, const float* __restrict__ w11,
                    const float* __restrict__ w12, const float* __restrict__ w20,
                    const float* __restrict__ w21, const float* __restrict__ w22,
                    const float* __restrict__ alphap,
                    float* __restrict__ out, int N, ResParams rp) {
    extern __shared__ char sm[];
    const int tid = threadIdx.x;
    const int wid = tid >> 5;
    const int lane = tid & 31;

    // ---- stage weight fragments (B-fragment order, bf16 hi/lo) ----
    {
        const float* Ws[5] = { w10, w11, w12, w20, w21 };
#pragma unroll 1
        for (int g = wid; g < 320; g += NWARP) {
            int layer = g >> 6;
            int rem = g & 63;
            int tile = rem >> 1;          // kt*8 + nt
            int j = rem & 1;              // b-register index
            int kt = tile >> 3;
            int k0 = kt * 16 + (lane & 3) * 2 + j * 8;
            int n = (tile & 7) * 8 + (lane >> 2);
            const float* W = Ws[layer];
            float v0 = __ldg(W + k0 * 64 + n);
            float v1 = __ldg(W + (k0 + 1) * 64 + n);
            uint32_t hi, lo;
            split2(v0, v1, hi, lo);
            char* base = sm + WFRAG_OFF + layer * 16384 + tile * 256 + lane * 8 + j * 4;
            *reinterpret_cast<uint32_t*>(base) = hi;
            *reinterpret_cast<uint32_t*>(base + 8192) = lo;
        }
        if (tid < 64) ((float*)(sm + W22_OFF))[tid] = w22[tid];
    }

    // ---- encode phase: feat row (bf16 hi/lo) into smem ----
    const int i = blockIdx.x * TPB + tid;
    const int ii = (i < N) ? i : (N - 1);
    const float x0 = x[3 * ii], x1 = x[3 * ii + 1], x2 = x[3 * ii + 2];
    const float tv = __ldg(tptr);
    char* myrow = sm + FEAT_OFF + tid * FEAT_STRIDE;

#pragma unroll 1
    for (int l = 0; l < NLEV; l++) {
        float a0, a1;
        enc3((const float2*)tbl_s + ((size_t)l << 19), x0, x1, x2, rp.r[l], a0, a1);
        uint32_t hi, lo;
        split2(a0, a1, hi, lo);
        *reinterpret_cast<uint32_t*>(myrow + 4 * l) = hi;
        *reinterpret_cast<uint32_t*>(myrow + 128 + 4 * l) = lo;
    }
#pragma unroll 1
    for (int l = 0; l < NLEV; l++) {
        float a0, a1;
        enc4((const float2*)tbl_d + ((size_t)l << 19), x0, x1, x2, tv, rp.r[l], a0, a1);
        uint32_t hi, lo;
        split2(a0, a1, hi, lo);
        *reinterpret_cast<uint32_t*>(myrow + 64 + 4 * l) = hi;
        *reinterpret_cast<uint32_t*>(myrow + 128 + 64 + 4 * l) = lo;
    }

    __syncthreads();

    // ---- warp-independent 5-layer MLP via HMMA ----
    const float alpha = __ldg(alphap);
    const float beta = 1.f - alpha;
    const int row_w = wid * 32;
    const int gq = lane >> 2;          // quad row 0..7
    const int cq = lane & 3;           // quad col 0..3

    uint32_t ahi[2][16], alo[2][16];   // next-layer A fragments per m-tile

#pragma unroll
    for (int layer = 0; layer < 5; layer++) {
#pragma unroll
        for (int mt = 0; mt < 2; mt++) {
            float d[8][4];
#pragma unroll
            for (int nt = 0; nt < 8; nt++)
#pragma unroll
                for (int q = 0; q < 4; q++) d[nt][q] = 0.f;

            const char* rp0 = sm + FEAT_OFF + (row_w + mt * 16 + gq) * FEAT_STRIDE;
            const char* rp8 = rp0 + 8 * FEAT_STRIDE;
            const char* wl = sm + WFRAG_OFF + layer * 16384;

#pragma unroll
            for (int kt = 0; kt < 4; kt++) {
                uint32_t Ah[4], Al[4];
                if (layer == 0) {
                    int cb = kt * 32 + cq * 4;
                    Ah[0] = *reinterpret_cast<const uint32_t*>(rp0 + cb);
                    Ah[1] = *reinterpret_cast<const uint32_t*>(rp8 + cb);
                    Ah[2] = *reinterpret_cast<const uint32_t*>(rp0 + cb + 16);
                    Ah[3] = *reinterpret_cast<const uint32_t*>(rp8 + cb + 16);
                    Al[0] = *reinterpret_cast<const uint32_t*>(rp0 + 128 + cb);
                    Al[1] = *reinterpret_cast<const uint32_t*>(rp8 + 128 + cb);
                    Al[2] = *reinterpret_cast<const uint32_t*>(rp0 + 128 + cb + 16);
                    Al[3] = *reinterpret_cast<const uint32_t*>(rp8 + 128 + cb + 16);
                } else {
#pragma unroll
                    for (int q = 0; q < 4; q++) {
                        Ah[q] = ahi[mt][kt * 4 + q];
                        Al[q] = alo[mt][kt * 4 + q];
                    }
                }
#pragma unroll
                for (int nt = 0; nt < 8; nt++) {
                    const char* tb = wl + (kt * 8 + nt) * 256 + lane * 8;
                    uint2 bh = *reinterpret_cast<const uint2*>(tb);
                    uint2 bl = *reinterpret_cast<const uint2*>(tb + 8192);
                    mma16816(d[nt], Ah, bh.x, bh.y);
                    mma16816(d[nt], Ah, bl.x, bl.y);
                    mma16816(d[nt], Al, bh.x, bh.y);
                }
            }

            if (layer < 4) {
                // ReLU (+ adaptive skip blend after layer 2), split into next A frags
#pragma unroll
                for (int nt = 0; nt < 8; nt++) {
#pragma unroll
                    for (int q = 0; q < 4; q++) d[nt][q] = fmaxf(d[nt][q], 0.f);
                    if (layer == 2) {
                        int cb = nt * 16 + cq * 4;
                        __nv_bfloat162 fh0 = *reinterpret_cast<const __nv_bfloat162*>(rp0 + cb);
                        __nv_bfloat162 fl0 = *reinterpret_cast<const __nv_bfloat162*>(rp0 + 128 + cb);
                        __nv_bfloat162 fh8 = *reinterpret_cast<const __nv_bfloat162*>(rp8 + cb);
                        __nv_bfloat162 fl8 = *reinterpret_cast<const __nv_bfloat162*>(rp8 + 128 + cb);
                        d[nt][0] = d[nt][0] * alpha + beta * (__bfloat162float(fh0.x) + __bfloat162float(fl0.x));
                        d[nt][1] = d[nt][1] * alpha + beta * (__bfloat162float(fh0.y) + __bfloat162float(fl0.y));
                        d[nt][2] = d[nt][2] * alpha + beta * (__bfloat162float(fh8.x) + __bfloat162float(fl8.x));
                        d[nt][3] = d[nt][3] * alpha + beta * (__bfloat162float(fh8.y) + __bfloat162float(fl8.y));
                    }
                }
#pragma unroll
                for (int kt = 0; kt < 4; kt++) {
                    split2(d[2 * kt][0],     d[2 * kt][1],     ahi[mt][kt * 4 + 0], alo[mt][kt * 4 + 0]);
                    split2(d[2 * kt][2],     d[2 * kt][3],     ahi[mt][kt * 4 + 1], alo[mt][kt * 4 + 1]);
                    split2(d[2 * kt + 1][0], d[2 * kt + 1][1], ahi[mt][kt * 4 + 2], alo[mt][kt * 4 + 2]);
                    split2(d[2 * kt + 1][2], d[2 * kt + 1][3], ahi[mt][kt * 4 + 3], alo[mt][kt * 4 + 3]);
                }
            } else {
                // final: ReLU + dot with w22, quad-reduce, store
                float s0 = 0.f, s1 = 0.f;
#pragma unroll
                for (int nt = 0; nt < 8; nt++) {
                    float2 wv = *reinterpret_cast<const float2*>(sm + W22_OFF + nt * 32 + cq * 8);
                    s0 = fmaf(fmaxf(d[nt][0], 0.f), wv.x, s0);
                    s0 = fmaf(fmaxf(d[nt][1], 0.f), wv.y, s0);
                    s1 = fmaf(fmaxf(d[nt][2], 0.f), wv.x, s1);
                    s1 = fmaf(fmaxf(d[nt][3], 0.f), wv.y, s1);
                }
                s0 += __shfl_xor_sync(0xFFFFFFFF, s0, 1);
                s0 += __shfl_xor_sync(0xFFFFFFFF, s0, 2);
                s1 += __shfl_xor_sync(0xFFFFFFFF, s1, 1);
                s1 += __shfl_xor_sync(0xFFFFFFFF, s1, 2);
                if (cq == 0) {
                    int r0 = blockIdx.x * TPB + row_w + mt * 16 + gq;
                    if (r0 < N) out[r0] = s0;
                    if (r0 + 8 < N) out[r0 + 8] = s1;
                }
            }
        }
    }
}

extern "C" void kernel_launch(void* const* d_in, const int* in_sizes, int n_in,
                              void* d_out, int out_size) {
    (void)in_sizes; (void)n_in;
    const float* x      = (const float*)d_in[0];
    const float* t      = (const float*)d_in[1];
    const float* tbl_s  = (const float*)d_in[2];
    const float* tbl_d  = (const float*)d_in[3];
    const float* w10    = (const float*)d_in[4];
    const float* w11    = (const float*)d_in[5];
    const float* w12    = (const float*)d_in[6];
    const float* w20    = (const float*)d_in[7];
    const float* w21    = (const float*)d_in[8];
    const float* w22    = (const float*)d_in[9];
    const float* alpha  = (const float*)d_in[10];
    float* out = (float*)d_out;

    const int N = out_size;
    if (N <= 0) return;

    // RES[l] = floor(16 * b^l), identical double-precision expr as reference
    ResParams rp;
    double b = pow(2048.0 / 16.0, 1.0 / 15.0);
    for (int l = 0; l < NLEV; l++)
        rp.r[l] = (int)floor(16.0 * pow(b, (double)l));

    cudaFuncSetAttribute(fused_hash_mlp_hmma,
                         cudaFuncAttributeMaxDynamicSharedMemorySize, SMEM_TOTAL);

    int blocks = (N + TPB - 1) / TPB;
    fused_hash_mlp_hmma<<<blocks, TPB, SMEM_TOTAL>>>(
        x, t, tbl_s, tbl_d, w10, w11, w12, w20, w21, w22, alpha, out, N, rp);
}

// round 5
// speedup vs baseline: 3.6289x; 1.4983x over previous
#include <cuda_runtime.h>
#include <cuda_bf16.h>
#include <math.h>
#include <stdint.h>

#define NLEV 16
#define TMASK ((1u << 19) - 1u)
#define PR1 2654435761u
#define PR2 805459861u
#define PR3 3674653429u
#define NMAX 2097152

// plane-major feature scratch: word c of point i at g_feat[c*NMAX + i]
// c in [0,32): bf16x2 hi words; c+32: lo words. 64 * 2M * 4B = 512 MB.
__device__ uint32_t g_feat[64ull * NMAX];

struct ResParams { int r[NLEV]; };

// ---------------- helpers ----------------
__device__ __forceinline__ void mma16816(float d[4], const uint32_t a[4], uint32_t b0, uint32_t b1) {
    asm volatile("mma.sync.aligned.m16n8k16.row.col.f32.bf16.bf16.f32 "
        "{%0,%1,%2,%3}, {%4,%5,%6,%7}, {%8,%9}, {%0,%1,%2,%3};"
        : "+f"(d[0]), "+f"(d[1]), "+f"(d[2]), "+f"(d[3])
        : "r"(a[0]), "r"(a[1]), "r"(a[2]), "r"(a[3]), "r"(b0), "r"(b1));
}

__device__ __forceinline__ void split2(float v0, float v1, uint32_t& hi, uint32_t& lo) {
    __nv_bfloat162 h, l;
    h.x = __float2bfloat16_rn(v0);
    h.y = __float2bfloat16_rn(v1);
    l.x = __float2bfloat16_rn(v0 - __bfloat162float(h.x));
    l.y = __float2bfloat16_rn(v1 - __bfloat162float(h.y));
    hi = *reinterpret_cast<uint32_t*>(&h);
    lo = *reinterpret_cast<uint32_t*>(&l);
}

__device__ __forceinline__ float bf2sum(uint32_t hi, uint32_t lo, int idx) {
    const __nv_bfloat162* h = reinterpret_cast<const __nv_bfloat162*>(&hi);
    const __nv_bfloat162* l = reinterpret_cast<const __nv_bfloat162*>(&lo);
    return idx == 0 ? (__bfloat162float(h->x) + __bfloat162float(l->x))
                    : (__bfloat162float(h->y) + __bfloat162float(l->y));
}

// ---------------- hash-grid level encoders (fp32, identical math to ref) ----------------
__device__ __forceinline__ void enc3(const float2* __restrict__ tb, float x0, float x1, float x2,
                                     int R, float& o0, float& o1) {
    float fr = (float)R;
    float p0 = x0 * fr, p1 = x1 * fr, p2 = x2 * fr;
    float g0 = floorf(p0), g1 = floorf(p1), g2 = floorf(p2);
    float f0 = p0 - g0, f1 = p1 - g1, f2 = p2 - g2;
    unsigned i0 = (unsigned)(int)g0, i1 = (unsigned)(int)g1, i2 = (unsigned)(int)g2;
    unsigned hx[2] = { i0, i0 + 1u };
    unsigned hy[2] = { i1 * PR1, (i1 + 1u) * PR1 };
    unsigned hz[2] = { i2 * PR2, (i2 + 1u) * PR2 };
    float wx[2] = { 1.f - f0, f0 };
    float wy[2] = { 1.f - f1, f1 };
    float wz[2] = { 1.f - f2, f2 };
    float2 v[8];
#pragma unroll
    for (int c = 0; c < 8; c++) {
        unsigned h = (hx[(c >> 2) & 1] ^ hy[(c >> 1) & 1] ^ hz[c & 1]) & TMASK;
        v[c] = __ldg(tb + h);
    }
    float a0 = 0.f, a1 = 0.f;
#pragma unroll
    for (int c = 0; c < 8; c++) {
        float w = wx[(c >> 2) & 1] * wy[(c >> 1) & 1];
        w *= wz[c & 1];
        a0 = fmaf(w, v[c].x, a0);
        a1 = fmaf(w, v[c].y, a1);
    }
    o0 = a0; o1 = a1;
}

__device__ __forceinline__ void enc4(const float2* __restrict__ tb, float x0, float x1, float x2, float x3,
                                     int R, float& o0, float& o1) {
    float fr = (float)R;
    float p0 = x0 * fr, p1 = x1 * fr, p2 = x2 * fr, p3 = x3 * fr;
    float g0 = floorf(p0), g1 = floorf(p1), g2 = floorf(p2), g3 = floorf(p3);
    float f0 = p0 - g0, f1 = p1 - g1, f2 = p2 - g2, f3 = p3 - g3;
    unsigned i0 = (unsigned)(int)g0, i1 = (unsigned)(int)g1;
    unsigned i2 = (unsigned)(int)g2, i3 = (unsigned)(int)g3;
    unsigned hx[2] = { i0, i0 + 1u };
    unsigned hy[2] = { i1 * PR1, (i1 + 1u) * PR1 };
    unsigned hz[2] = { i2 * PR2, (i2 + 1u) * PR2 };
    unsigned hw[2] = { i3 * PR3, (i3 + 1u) * PR3 };
    float wx[2] = { 1.f - f0, f0 };
    float wy[2] = { 1.f - f1, f1 };
    float wz[2] = { 1.f - f2, f2 };
    float ww[2] = { 1.f - f3, f3 };
    float2 v[16];
#pragma unroll
    for (int c = 0; c < 16; c++) {
        unsigned h = (hx[(c >> 3) & 1] ^ hy[(c >> 2) & 1] ^ hz[(c >> 1) & 1] ^ hw[c & 1]) & TMASK;
        v[c] = __ldg(tb + h);
    }
    float a0 = 0.f, a1 = 0.f;
#pragma unroll
    for (int c = 0; c < 16; c++) {
        float w = wx[(c >> 3) & 1] * wy[(c >> 2) & 1];
        w *= wz[(c >> 1) & 1];
        w *= ww[c & 1];
        a0 = fmaf(w, v[c].x, a0);
        a1 = fmaf(w, v[c].y, a1);
    }
    o0 = a0; o1 = a1;
}

// ================= kernel A: hash-grid encode -> plane-major scratch =================
__global__ void __launch_bounds__(256)
encode_kernel(const float* __restrict__ x,
              const float* __restrict__ tptr,
              const float* __restrict__ tbl_s,
              const float* __restrict__ tbl_d,
              int N, ResParams rp) {
    const int i = blockIdx.x * 256 + threadIdx.x;
    if (i >= N) return;
    const float x0 = x[3 * i], x1 = x[3 * i + 1], x2 = x[3 * i + 2];
    const float tv = __ldg(tptr);

#pragma unroll 1
    for (int l = 0; l < NLEV; l++) {
        float a0, a1;
        enc3((const float2*)tbl_s + ((size_t)l << 19), x0, x1, x2, rp.r[l], a0, a1);
        uint32_t hi, lo;
        split2(a0, a1, hi, lo);
        g_feat[(size_t)l * NMAX + i] = hi;
        g_feat[(size_t)(32 + l) * NMAX + i] = lo;
    }
#pragma unroll 1
    for (int l = 0; l < NLEV; l++) {
        float a0, a1;
        enc4((const float2*)tbl_d + ((size_t)l << 19), x0, x1, x2, tv, rp.r[l], a0, a1);
        uint32_t hi, lo;
        split2(a0, a1, hi, lo);
        g_feat[(size_t)(16 + l) * NMAX + i] = hi;
        g_feat[(size_t)(48 + l) * NMAX + i] = lo;
    }
}

// ================= kernel B: 5-layer MLP via HMMA =================
#define BTPB 256
#define BWARP 8
#define W22_OFF 81920
#define BSMEM (81920 + 256)

__global__ void __launch_bounds__(BTPB, 2)
mlp_kernel(const float* __restrict__ w10, const float* __restrict__ w11,
           const float* __restrict__ w12, const float* __restrict__ w20,
           const float* __restrict__ w21, const float* __restrict__ w22,
           const float* __restrict__ alphap,
           float* __restrict__ out, int N) {
    extern __shared__ char sm[];
    const int tid = threadIdx.x;
    const int wid = tid >> 5;
    const int lane = tid & 31;
    const int gq = lane >> 2;   // quad row 0..7
    const int cq = lane & 3;    // quad col 0..3

    // ---- stage weight fragments (B-fragment order, bf16 hi/lo) ----
    {
        const float* Ws[5] = { w10, w11, w12, w20, w21 };
#pragma unroll 1
        for (int g = wid; g < 320; g += BWARP) {
            int layer = g >> 6;
            int rem = g & 63;
            int tile = rem >> 1;          // kt*8 + nt
            int j = rem & 1;
            int kt = tile >> 3;
            int k0 = kt * 16 + cq * 2 + j * 8;
            int n = (tile & 7) * 8 + gq;
            const float* W = Ws[layer];
            float v0 = __ldg(W + k0 * 64 + n);
            float v1 = __ldg(W + (k0 + 1) * 64 + n);
            uint32_t hi, lo;
            split2(v0, v1, hi, lo);
            char* base = sm + layer * 16384 + tile * 256 + lane * 8 + j * 4;
            *reinterpret_cast<uint32_t*>(base) = hi;
            *reinterpret_cast<uint32_t*>(base + 8192) = lo;
        }
        if (tid < 64) ((float*)(sm + W22_OFF))[tid] = w22[tid];
    }
    __syncthreads();

    const float alpha = __ldg(alphap);
    const float beta = 1.f - alpha;

#pragma unroll 1
    for (int mt = 0; mt < 2; mt++) {
        const int base_row = blockIdx.x * BTPB + wid * 32 + mt * 16;
        uint32_t ahi[16], alo[16];

#pragma unroll
        for (int layer = 0; layer < 5; layer++) {
            float d[8][4];
#pragma unroll
            for (int nt = 0; nt < 8; nt++)
#pragma unroll
                for (int q = 0; q < 4; q++) d[nt][q] = 0.f;

            const char* wl = sm + layer * 16384;

#pragma unroll
            for (int kt = 0; kt < 4; kt++) {
                uint32_t Ah[4], Al[4];
                if (layer == 0) {
                    size_t p0 = (size_t)(kt * 8 + cq) * NMAX + base_row + gq;
                    Ah[0] = g_feat[p0];
                    Ah[1] = g_feat[p0 + 8];
                    Ah[2] = g_feat[p0 + 4ull * NMAX];
                    Ah[3] = g_feat[p0 + 4ull * NMAX + 8];
                    Al[0] = g_feat[p0 + 32ull * NMAX];
                    Al[1] = g_feat[p0 + 32ull * NMAX + 8];
                    Al[2] = g_feat[p0 + 36ull * NMAX];
                    Al[3] = g_feat[p0 + 36ull * NMAX + 8];
                } else {
#pragma unroll
                    for (int q = 0; q < 4; q++) { Ah[q] = ahi[kt * 4 + q]; Al[q] = alo[kt * 4 + q]; }
                }
#pragma unroll
                for (int nt = 0; nt < 8; nt++) {
                    const char* tb = wl + (kt * 8 + nt) * 256 + lane * 8;
                    uint2 bh = *reinterpret_cast<const uint2*>(tb);
                    uint2 bl = *reinterpret_cast<const uint2*>(tb + 8192);
                    mma16816(d[nt], Ah, bh.x, bh.y);
                    mma16816(d[nt], Ah, bl.x, bl.y);
                    mma16816(d[nt], Al, bh.x, bh.y);
                }
            }

            if (layer < 4) {
#pragma unroll
                for (int nt = 0; nt < 8; nt++) {
#pragma unroll
                    for (int q = 0; q < 4; q++) d[nt][q] = fmaxf(d[nt][q], 0.f);
                    if (layer == 2) {
                        size_t pw = (size_t)(nt * 4 + cq) * NMAX + base_row + gq;
                        uint32_t h0 = g_feat[pw],               l0 = g_feat[pw + 32ull * NMAX];
                        uint32_t h8 = g_feat[pw + 8],           l8 = g_feat[pw + 32ull * NMAX + 8];
                        d[nt][0] = d[nt][0] * alpha + beta * bf2sum(h0, l0, 0);
                        d[nt][1] = d[nt][1] * alpha + beta * bf2sum(h0, l0, 1);
                        d[nt][2] = d[nt][2] * alpha + beta * bf2sum(h8, l8, 0);
                        d[nt][3] = d[nt][3] * alpha + beta * bf2sum(h8, l8, 1);
                    }
                }
#pragma unroll
                for (int kt = 0; kt < 4; kt++) {
                    split2(d[2 * kt][0],     d[2 * kt][1],     ahi[kt * 4 + 0], alo[kt * 4 + 0]);
                    split2(d[2 * kt][2],     d[2 * kt][3],     ahi[kt * 4 + 1], alo[kt * 4 + 1]);
                    split2(d[2 * kt + 1][0], d[2 * kt + 1][1], ahi[kt * 4 + 2], alo[kt * 4 + 2]);
                    split2(d[2 * kt + 1][2], d[2 * kt + 1][3], ahi[kt * 4 + 3], alo[kt * 4 + 3]);
                }
            } else {
                float s0 = 0.f, s1 = 0.f;
#pragma unroll
                for (int nt = 0; nt < 8; nt++) {
                    float2 wv = *reinterpret_cast<const float2*>(sm + W22_OFF + nt * 32 + cq * 8);
                    s0 = fmaf(fmaxf(d[nt][0], 0.f), wv.x, s0);
                    s0 = fmaf(fmaxf(d[nt][1], 0.f), wv.y, s0);
                    s1 = fmaf(fmaxf(d[nt][2], 0.f), wv.x, s1);
                    s1 = fmaf(fmaxf(d[nt][3], 0.f), wv.y, s1);
                }
                s0 += __shfl_xor_sync(0xFFFFFFFF, s0, 1);
                s0 += __shfl_xor_sync(0xFFFFFFFF, s0, 2);
                s1 += __shfl_xor_sync(0xFFFFFFFF, s1, 1);
                s1 += __shfl_xor_sync(0xFFFFFFFF, s1, 2);
                if (cq == 0) {
                    int r0 = base_row + gq;
                    if (r0 < N) out[r0] = s0;
                    if (r0 + 8 < N) out[r0 + 8] = s1;
                }
            }
        }
    }
}

extern "C" void kernel_launch(void* const* d_in, const int* in_sizes, int n_in,
                              void* d_out, int out_size) {
    (void)in_sizes; (void)n_in;
    const float* x      = (const float*)d_in[0];
    const float* t      = (const float*)d_in[1];
    const float* tbl_s  = (const float*)d_in[2];
    const float* tbl_d  = (const float*)d_in[3];
    const float* w10    = (const float*)d_in[4];
    const float* w11    = (const float*)d_in[5];
    const float* w12    = (const float*)d_in[6];
    const float* w20    = (const float*)d_in[7];
    const float* w21    = (const float*)d_in[8];
    const float* w22    = (const float*)d_in[9];
    const float* alpha  = (const float*)d_in[10];
    float* out = (float*)d_out;

    int N = out_size;
    if (N <= 0) return;
    if (N > NMAX) N = NMAX;

    // RES[l] = floor(16 * b^l), identical double-precision expr as reference
    ResParams rp;
    double b = pow(2048.0 / 16.0, 1.0 / 15.0);
    for (int l = 0; l < NLEV; l++)
        rp.r[l] = (int)floor(16.0 * pow(b, (double)l));

    int blocksA = (N + 255) / 256;
    encode_kernel<<<blocksA, 256>>>(x, t, tbl_s, tbl_d, N, rp);

    cudaFuncSetAttribute(mlp_kernel, cudaFuncAttributeMaxDynamicSharedMemorySize, BSMEM);
    int blocksB = (N + BTPB - 1) / BTPB;
    mlp_kernel<<<blocksB, BTPB, BSMEM>>>(w10, w11, w12, w20, w21, w22, alpha, out, N);
}

// round 6
// speedup vs baseline: 4.0616x; 1.1192x over previous
#include <cuda_runtime.h>
#include <cuda_bf16.h>
#include <math.h>
#include <stdint.h>

#define NLEV 16
#define TMASK ((1u << 19) - 1u)
#define PR1 2654435761u
#define PR2 805459861u
#define PR3 3674653429u
#define NMAX 2097152

// plane-major feature scratch: word c of point i at g_feat[c*NMAX + i]
// c in [0,32): bf16x2 hi words; c+32: lo words. 64 * 2M * 4B = 512 MB.
__device__ uint32_t g_feat[64ull * NMAX];

struct ResParams { int r[NLEV]; };

// ---------------- helpers ----------------
__device__ __forceinline__ void mma16816(float d[4], const uint32_t a[4], uint32_t b0, uint32_t b1) {
    asm volatile("mma.sync.aligned.m16n8k16.row.col.f32.bf16.bf16.f32 "
        "{%0,%1,%2,%3}, {%4,%5,%6,%7}, {%8,%9}, {%0,%1,%2,%3};"
        : "+f"(d[0]), "+f"(d[1]), "+f"(d[2]), "+f"(d[3])
        : "r"(a[0]), "r"(a[1]), "r"(a[2]), "r"(a[3]), "r"(b0), "r"(b1));
}

__device__ __forceinline__ void split2(float v0, float v1, uint32_t& hi, uint32_t& lo) {
    __nv_bfloat162 h, l;
    h.x = __float2bfloat16_rn(v0);
    h.y = __float2bfloat16_rn(v1);
    l.x = __float2bfloat16_rn(v0 - __bfloat162float(h.x));
    l.y = __float2bfloat16_rn(v1 - __bfloat162float(h.y));
    hi = *reinterpret_cast<uint32_t*>(&h);
    lo = *reinterpret_cast<uint32_t*>(&l);
}

__device__ __forceinline__ float bf2sum(uint32_t hi, uint32_t lo, int idx) {
    const __nv_bfloat162* h = reinterpret_cast<const __nv_bfloat162*>(&hi);
    const __nv_bfloat162* l = reinterpret_cast<const __nv_bfloat162*>(&lo);
    return idx == 0 ? (__bfloat162float(h->x) + __bfloat162float(l->x))
                    : (__bfloat162float(h->y) + __bfloat162float(l->y));
}

// ---------------- hash-grid level encoders (fp32, identical math to ref) ----------------
__device__ __forceinline__ void enc3(const float2* __restrict__ tb, float x0, float x1, float x2,
                                     int R, float& o0, float& o1) {
    float fr = (float)R;
    float p0 = x0 * fr, p1 = x1 * fr, p2 = x2 * fr;
    float g0 = floorf(p0), g1 = floorf(p1), g2 = floorf(p2);
    float f0 = p0 - g0, f1 = p1 - g1, f2 = p2 - g2;
    unsigned i0 = (unsigned)(int)g0, i1 = (unsigned)(int)g1, i2 = (unsigned)(int)g2;
    unsigned hx[2] = { i0, i0 + 1u };
    unsigned hy[2] = { i1 * PR1, (i1 + 1u) * PR1 };
    unsigned hz[2] = { i2 * PR2, (i2 + 1u) * PR2 };
    float wx[2] = { 1.f - f0, f0 };
    float wy[2] = { 1.f - f1, f1 };
    float wz[2] = { 1.f - f2, f2 };
    float2 v[8];
#pragma unroll
    for (int c = 0; c < 8; c++) {
        unsigned h = (hx[(c >> 2) & 1] ^ hy[(c >> 1) & 1] ^ hz[c & 1]) & TMASK;
        v[c] = __ldg(tb + h);
    }
    float a0 = 0.f, a1 = 0.f;
#pragma unroll
    for (int c = 0; c < 8; c++) {
        float w = wx[(c >> 2) & 1] * wy[(c >> 1) & 1];
        w *= wz[c & 1];
        a0 = fmaf(w, v[c].x, a0);
        a1 = fmaf(w, v[c].y, a1);
    }
    o0 = a0; o1 = a1;
}

__device__ __forceinline__ void enc4(const float2* __restrict__ tb, float x0, float x1, float x2, float x3,
                                     int R, float& o0, float& o1) {
    float fr = (float)R;
    float p0 = x0 * fr, p1 = x1 * fr, p2 = x2 * fr, p3 = x3 * fr;
    float g0 = floorf(p0), g1 = floorf(p1), g2 = floorf(p2), g3 = floorf(p3);
    float f0 = p0 - g0, f1 = p1 - g1, f2 = p2 - g2, f3 = p3 - g3;
    unsigned i0 = (unsigned)(int)g0, i1 = (unsigned)(int)g1;
    unsigned i2 = (unsigned)(int)g2, i3 = (unsigned)(int)g3;
    unsigned hx[2] = { i0, i0 + 1u };
    unsigned hy[2] = { i1 * PR1, (i1 + 1u) * PR1 };
    unsigned hz[2] = { i2 * PR2, (i2 + 1u) * PR2 };
    unsigned hw[2] = { i3 * PR3, (i3 + 1u) * PR3 };
    float wx[2] = { 1.f - f0, f0 };
    float wy[2] = { 1.f - f1, f1 };
    float wz[2] = { 1.f - f2, f2 };
    float ww[2] = { 1.f - f3, f3 };
    float2 v[16];
#pragma unroll
    for (int c = 0; c < 16; c++) {
        unsigned h = (hx[(c >> 3) & 1] ^ hy[(c >> 2) & 1] ^ hz[(c >> 1) & 1] ^ hw[c & 1]) & TMASK;
        v[c] = __ldg(tb + h);
    }
    float a0 = 0.f, a1 = 0.f;
#pragma unroll
    for (int c = 0; c < 16; c++) {
        float w = wx[(c >> 3) & 1] * wy[(c >> 2) & 1];
        w *= wz[(c >> 1) & 1];
        w *= ww[c & 1];
        a0 = fmaf(w, v[c].x, a0);
        a1 = fmaf(w, v[c].y, a1);
    }
    o0 = a0; o1 = a1;
}

// ================= kernel A: level-parallel hash-grid encode =================
// grid = (ceil(N/256), 32): blockIdx.y = level slot (0-15 static 3D, 16-31 dynamic 4D)
__global__ void __launch_bounds__(256)
encode_kernel(const float* __restrict__ x,
              const float* __restrict__ tptr,
              const float* __restrict__ tbl_s,
              const float* __restrict__ tbl_d,
              int N, ResParams rp) {
    const int i = blockIdx.x * 256 + threadIdx.x;
    if (i >= N) return;
    const int lv = blockIdx.y;

    const float x0 = x[3 * i], x1 = x[3 * i + 1], x2 = x[3 * i + 2];
    float a0, a1;
    size_t hi_plane, lo_plane;

    if (lv < 16) {
        enc3((const float2*)tbl_s + ((size_t)lv << 19), x0, x1, x2, rp.r[lv], a0, a1);
        hi_plane = (size_t)lv * NMAX;
        lo_plane = (size_t)(32 + lv) * NMAX;
    } else {
        const int l = lv - 16;
        const float tv = __ldg(tptr);
        enc4((const float2*)tbl_d + ((size_t)l << 19), x0, x1, x2, tv, rp.r[l], a0, a1);
        hi_plane = (size_t)(16 + l) * NMAX;
        lo_plane = (size_t)(48 + l) * NMAX;
    }

    uint32_t hi, lo;
    split2(a0, a1, hi, lo);
    g_feat[hi_plane + i] = hi;
    g_feat[lo_plane + i] = lo;
}

// ================= kernel B: 5-layer MLP via HMMA =================
#define BTPB 256
#define BWARP 8
#define W22_OFF 81920
#define BSMEM (81920 + 256)

__global__ void __launch_bounds__(BTPB, 2)
mlp_kernel(const float* __restrict__ w10, const float* __restrict__ w11,
           const float* __restrict__ w12, const float* __restrict__ w20,
           const float* __restrict__ w21, const float* __restrict__ w22,
           const float* __restrict__ alphap,
           float* __restrict__ out, int N) {
    extern __shared__ char sm[];
    const int tid = threadIdx.x;
    const int wid = tid >> 5;
    const int lane = tid & 31;
    const int gq = lane >> 2;   // quad row 0..7
    const int cq = lane & 3;    // quad col 0..3

    // ---- stage weight fragments (B-fragment order, bf16 hi/lo) ----
    {
        const float* Ws[5] = { w10, w11, w12, w20, w21 };
#pragma unroll 1
        for (int g = wid; g < 320; g += BWARP) {
            int layer = g >> 6;
            int rem = g & 63;
            int tile = rem >> 1;          // kt*8 + nt
            int j = rem & 1;
            int kt = tile >> 3;
            int k0 = kt * 16 + cq * 2 + j * 8;
            int n = (tile & 7) * 8 + gq;
            const float* W = Ws[layer];
            float v0 = __ldg(W + k0 * 64 + n);
            float v1 = __ldg(W + (k0 + 1) * 64 + n);
            uint32_t hi, lo;
            split2(v0, v1, hi, lo);
            char* base = sm + layer * 16384 + tile * 256 + lane * 8 + j * 4;
            *reinterpret_cast<uint32_t*>(base) = hi;
            *reinterpret_cast<uint32_t*>(base + 8192) = lo;
        }
        if (tid < 64) ((float*)(sm + W22_OFF))[tid] = w22[tid];
    }
    __syncthreads();

    const float alpha = __ldg(alphap);
    const float beta = 1.f - alpha;

#pragma unroll 1
    for (int mt = 0; mt < 2; mt++) {
        const int base_row = blockIdx.x * BTPB + wid * 32 + mt * 16;
        uint32_t ahi[16], alo[16];

#pragma unroll
        for (int layer = 0; layer < 5; layer++) {
            float d[8][4];
#pragma unroll
            for (int nt = 0; nt < 8; nt++)
#pragma unroll
                for (int q = 0; q < 4; q++) d[nt][q] = 0.f;

            const char* wl = sm + layer * 16384;

#pragma unroll
            for (int kt = 0; kt < 4; kt++) {
                uint32_t Ah[4], Al[4];
                if (layer == 0) {
                    size_t p0 = (size_t)(kt * 8 + cq) * NMAX + base_row + gq;
                    Ah[0] = g_feat[p0];
                    Ah[1] = g_feat[p0 + 8];
                    Ah[2] = g_feat[p0 + 4ull * NMAX];
                    Ah[3] = g_feat[p0 + 4ull * NMAX + 8];
                    Al[0] = g_feat[p0 + 32ull * NMAX];
                    Al[1] = g_feat[p0 + 32ull * NMAX + 8];
                    Al[2] = g_feat[p0 + 36ull * NMAX];
                    Al[3] = g_feat[p0 + 36ull * NMAX + 8];
                } else {
#pragma unroll
                    for (int q = 0; q < 4; q++) { Ah[q] = ahi[kt * 4 + q]; Al[q] = alo[kt * 4 + q]; }
                }
#pragma unroll
                for (int nt = 0; nt < 8; nt++) {
                    const char* tb = wl + (kt * 8 + nt) * 256 + lane * 8;
                    uint2 bh = *reinterpret_cast<const uint2*>(tb);
                    uint2 bl = *reinterpret_cast<const uint2*>(tb + 8192);
                    mma16816(d[nt], Ah, bh.x, bh.y);
                    mma16816(d[nt], Ah, bl.x, bl.y);
                    mma16816(d[nt], Al, bh.x, bh.y);
                }
            }

            if (layer < 4) {
#pragma unroll
                for (int nt = 0; nt < 8; nt++) {
#pragma unroll
                    for (int q = 0; q < 4; q++) d[nt][q] = fmaxf(d[nt][q], 0.f);
                    if (layer == 2) {
                        size_t pw = (size_t)(nt * 4 + cq) * NMAX + base_row + gq;
                        uint32_t h0 = g_feat[pw],     l0 = g_feat[pw + 32ull * NMAX];
                        uint32_t h8 = g_feat[pw + 8], l8 = g_feat[pw + 32ull * NMAX + 8];
                        d[nt][0] = d[nt][0] * alpha + beta * bf2sum(h0, l0, 0);
                        d[nt][1] = d[nt][1] * alpha + beta * bf2sum(h0, l0, 1);
                        d[nt][2] = d[nt][2] * alpha + beta * bf2sum(h8, l8, 0);
                        d[nt][3] = d[nt][3] * alpha + beta * bf2sum(h8, l8, 1);
                    }
                }
#pragma unroll
                for (int kt = 0; kt < 4; kt++) {
                    split2(d[2 * kt][0],     d[2 * kt][1],     ahi[kt * 4 + 0], alo[kt * 4 + 0]);
                    split2(d[2 * kt][2],     d[2 * kt][3],     ahi[kt * 4 + 1], alo[kt * 4 + 1]);
                    split2(d[2 * kt + 1][0], d[2 * kt + 1][1], ahi[kt * 4 + 2], alo[kt * 4 + 2]);
                    split2(d[2 * kt + 1][2], d[2 * kt + 1][3], ahi[kt * 4 + 3], alo[kt * 4 + 3]);
                }
            } else {
                float s0 = 0.f, s1 = 0.f;
#pragma unroll
                for (int nt = 0; nt < 8; nt++) {
                    float2 wv = *reinterpret_cast<const float2*>(sm + W22_OFF + nt * 32 + cq * 8);
                    s0 = fmaf(fmaxf(d[nt][0], 0.f), wv.x, s0);
                    s0 = fmaf(fmaxf(d[nt][1], 0.f), wv.y, s0);
                    s1 = fmaf(fmaxf(d[nt][2], 0.f), wv.x, s1);
                    s1 = fmaf(fmaxf(d[nt][3], 0.f), wv.y, s1);
                }
                s0 += __shfl_xor_sync(0xFFFFFFFF, s0, 1);
                s0 += __shfl_xor_sync(0xFFFFFFFF, s0, 2);
                s1 += __shfl_xor_sync(0xFFFFFFFF, s1, 1);
                s1 += __shfl_xor_sync(0xFFFFFFFF, s1, 2);
                if (cq == 0) {
                    int r0 = base_row + gq;
                    if (r0 < N) out[r0] = s0;
                    if (r0 + 8 < N) out[r0 + 8] = s1;
                }
            }
        }
    }
}

extern "C" void kernel_launch(void* const* d_in, const int* in_sizes, int n_in,
                              void* d_out, int out_size) {
    (void)in_sizes; (void)n_in;
    const float* x      = (const float*)d_in[0];
    const float* t      = (const float*)d_in[1];
    const float* tbl_s  = (const float*)d_in[2];
    const float* tbl_d  = (const float*)d_in[3];
    const float* w10    = (const float*)d_in[4];
    const float* w11    = (const float*)d_in[5];
    const float* w12    = (const float*)d_in[6];
    const float* w20    = (const float*)d_in[7];
    const float* w21    = (const float*)d_in[8];
    const float* w22    = (const float*)d_in[9];
    const float* alpha  = (const float*)d_in[10];
    float* out = (float*)d_out;

    int N = out_size;
    if (N <= 0) return;
    if (N > NMAX) N = NMAX;

    // RES[l] = floor(16 * b^l), identical double-precision expr as reference
    ResParams rp;
    double b = pow(2048.0 / 16.0, 1.0 / 15.0);
    for (int l = 0; l < NLEV; l++)
        rp.r[l] = (int)floor(16.0 * pow(b, (double)l));

    dim3 gridA((N + 255) / 256, 32);
    encode_kernel<<<gridA, 256>>>(x, t, tbl_s, tbl_d, N, rp);

    cudaFuncSetAttribute(mlp_kernel, cudaFuncAttributeMaxDynamicSharedMemorySize, BSMEM);
    int blocksB = (N + BTPB - 1) / BTPB;
    mlp_kernel<<<blocksB, BTPB, BSMEM>>>(w10, w11, w12, w20, w21, w22, alpha, out, N);
}

// round 7
// speedup vs baseline: 5.0597x; 1.2458x over previous
#include <cuda_runtime.h>
#include <cuda_bf16.h>
#include <math.h>
#include <stdint.h>

#define NLEV 16
#define TMASK ((1u << 19) - 1u)
#define PR1 2654435761u
#define PR2 805459861u
#define PR3 3674653429u
#define NMAX 2097152

// plane-major feature scratch: word c of point i at g_feat[c*NMAX + i]
// c in [0,32): bf16x2 hi words; c+32: lo words. 64 * 2M * 4B = 512 MB.
__device__ uint32_t g_feat[64ull * NMAX];

struct ResParams { int r[NLEV]; };

// ---------------- helpers ----------------
__device__ __forceinline__ void mma16816(float d[4], const uint32_t a[4], uint32_t b0, uint32_t b1) {
    asm volatile("mma.sync.aligned.m16n8k16.row.col.f32.bf16.bf16.f32 "
        "{%0,%1,%2,%3}, {%4,%5,%6,%7}, {%8,%9}, {%0,%1,%2,%3};"
        : "+f"(d[0]), "+f"(d[1]), "+f"(d[2]), "+f"(d[3])
        : "r"(a[0]), "r"(a[1]), "r"(a[2]), "r"(a[3]), "r"(b0), "r"(b1));
}

__device__ __forceinline__ void split2(float v0, float v1, uint32_t& hi, uint32_t& lo) {
    __nv_bfloat162 h, l;
    h.x = __float2bfloat16_rn(v0);
    h.y = __float2bfloat16_rn(v1);
    l.x = __float2bfloat16_rn(v0 - __bfloat162float(h.x));
    l.y = __float2bfloat16_rn(v1 - __bfloat162float(h.y));
    hi = *reinterpret_cast<uint32_t*>(&h);
    lo = *reinterpret_cast<uint32_t*>(&l);
}

__device__ __forceinline__ float bf2sum(uint32_t hi, uint32_t lo, int idx) {
    const __nv_bfloat162* h = reinterpret_cast<const __nv_bfloat162*>(&hi);
    const __nv_bfloat162* l = reinterpret_cast<const __nv_bfloat162*>(&lo);
    return idx == 0 ? (__bfloat162float(h->x) + __bfloat162float(l->x))
                    : (__bfloat162float(h->y) + __bfloat162float(l->y));
}

// elementwise float2 lerp: a + f*(b-a)
__device__ __forceinline__ float2 lerp2(float2 a, float2 b, float f) {
    float2 r;
    r.x = fmaf(f, b.x - a.x, a.x);
    r.y = fmaf(f, b.y - a.y, a.y);
    return r;
}

// ---------------- hash-grid level encoders (factored lerp tree) ----------------
__device__ __forceinline__ void enc3(const float2* __restrict__ tb, float x0, float x1, float x2,
                                     int R, float& o0, float& o1) {
    float fr = (float)R;
    float p0 = x0 * fr, p1 = x1 * fr, p2 = x2 * fr;
    float g0 = floorf(p0), g1 = floorf(p1), g2 = floorf(p2);
    float f0 = p0 - g0, f1 = p1 - g1, f2 = p2 - g2;
    unsigned i0 = (unsigned)(int)g0, i1 = (unsigned)(int)g1, i2 = (unsigned)(int)g2;
    unsigned hy0 = i1 * PR1, hy1 = hy0 + PR1;
    unsigned hz0 = i2 * PR2, hz1 = hz0 + PR2;
    unsigned hyz[4] = { hy0 ^ hz0, hy0 ^ hz1, hy1 ^ hz0, hy1 ^ hz1 };
    unsigned i0b = i0 + 1u;
    // v index: x<<2 | y<<1 | z
    float2 v[8];
#pragma unroll
    for (int j = 0; j < 4; j++) {
        v[j]     = __ldg(tb + ((i0  ^ hyz[j]) & TMASK));
        v[4 + j] = __ldg(tb + ((i0b ^ hyz[j]) & TMASK));
    }
    float2 u0 = lerp2(v[0], v[4], f0);
    float2 u1 = lerp2(v[1], v[5], f0);
    float2 u2 = lerp2(v[2], v[6], f0);
    float2 u3 = lerp2(v[3], v[7], f0);
    float2 s0 = lerp2(u0, u2, f1);
    float2 s1 = lerp2(u1, u3, f1);
    float2 r  = lerp2(s0, s1, f2);
    o0 = r.x; o1 = r.y;
}

__device__ __forceinline__ void enc4(const float2* __restrict__ tb, float x0, float x1, float x2, float x3,
                                     int R, float& o0, float& o1) {
    float fr = (float)R;
    float p0 = x0 * fr, p1 = x1 * fr, p2 = x2 * fr, p3 = x3 * fr;
    float g0 = floorf(p0), g1 = floorf(p1), g2 = floorf(p2), g3 = floorf(p3);
    float f0 = p0 - g0, f1 = p1 - g1, f2 = p2 - g2, f3 = p3 - g3;
    unsigned i0 = (unsigned)(int)g0, i1 = (unsigned)(int)g1;
    unsigned i2 = (unsigned)(int)g2, i3 = (unsigned)(int)g3;
    unsigned hy0 = i1 * PR1, hy1 = hy0 + PR1;
    unsigned hz0 = i2 * PR2, hz1 = hz0 + PR2;
    unsigned hw0 = i3 * PR3, hw1 = hw0 + PR3;
    unsigned hzw[4] = { hz0 ^ hw0, hz0 ^ hw1, hz1 ^ hw0, hz1 ^ hw1 };
    unsigned hyzw[8];
#pragma unroll
    for (int j = 0; j < 4; j++) { hyzw[j] = hy0 ^ hzw[j]; hyzw[4 + j] = hy1 ^ hzw[j]; }
    unsigned i0b = i0 + 1u;
    // v index: x<<3 | y<<2 | z<<1 | w
    float2 v[16];
#pragma unroll
    for (int j = 0; j < 8; j++) {
        v[j]     = __ldg(tb + ((i0  ^ hyzw[j]) & TMASK));
        v[8 + j] = __ldg(tb + ((i0b ^ hyzw[j]) & TMASK));
    }
    float2 u[8];
#pragma unroll
    for (int j = 0; j < 8; j++) u[j] = lerp2(v[j], v[8 + j], f0);
    float2 s[4];
#pragma unroll
    for (int j = 0; j < 4; j++) s[j] = lerp2(u[j], u[4 + j], f1);
    float2 r0 = lerp2(s[0], s[2], f2);
    float2 r1 = lerp2(s[1], s[3], f2);
    float2 r  = lerp2(r0, r1, f3);
    o0 = r.x; o1 = r.y;
}

// ================= kernel A: level-parallel hash-grid encode =================
// grid = (ceil(N/256), 32): blockIdx.y = level slot (0-15 static 3D, 16-31 dynamic 4D)
__global__ void __launch_bounds__(256)
encode_kernel(const float* __restrict__ x,
              const float* __restrict__ tptr,
              const float* __restrict__ tbl_s,
              const float* __restrict__ tbl_d,
              int N, ResParams rp) {
    const int i = blockIdx.x * 256 + threadIdx.x;
    if (i >= N) return;
    const int lv = blockIdx.y;

    const float x0 = x[3 * i], x1 = x[3 * i + 1], x2 = x[3 * i + 2];
    float a0, a1;
    size_t hi_plane, lo_plane;

    if (lv < 16) {
        enc3((const float2*)tbl_s + ((size_t)lv << 19), x0, x1, x2, rp.r[lv], a0, a1);
        hi_plane = (size_t)lv * NMAX;
        lo_plane = (size_t)(32 + lv) * NMAX;
    } else {
        const int l = lv - 16;
        const float tv = __ldg(tptr);
        enc4((const float2*)tbl_d + ((size_t)l << 19), x0, x1, x2, tv, rp.r[l], a0, a1);
        hi_plane = (size_t)(16 + l) * NMAX;
        lo_plane = (size_t)(48 + l) * NMAX;
    }

    uint32_t hi, lo;
    split2(a0, a1, hi, lo);
    // evict-first streaming stores: don't let the 512MB scratch evict the hash tables from L2
    __stcs(&g_feat[hi_plane + i], hi);
    __stcs(&g_feat[lo_plane + i], lo);
}

// ================= kernel B: 5-layer MLP via HMMA =================
#define BTPB 256
#define BWARP 8
#define W22_OFF 81920
#define BSMEM (81920 + 256)

__global__ void __launch_bounds__(BTPB, 2)
mlp_kernel(const float* __restrict__ w10, const float* __restrict__ w11,
           const float* __restrict__ w12, const float* __restrict__ w20,
           const float* __restrict__ w21, const float* __restrict__ w22,
           const float* __restrict__ alphap,
           float* __restrict__ out, int N) {
    extern __shared__ char sm[];
    const int tid = threadIdx.x;
    const int wid = tid >> 5;
    const int lane = tid & 31;
    const int gq = lane >> 2;   // quad row 0..7
    const int cq = lane & 3;    // quad col 0..3

    // ---- stage weight fragments (B-fragment order, bf16 hi/lo) ----
    {
        const float* Ws[5] = { w10, w11, w12, w20, w21 };
#pragma unroll 1
        for (int g = wid; g < 320; g += BWARP) {
            int layer = g >> 6;
            int rem = g & 63;
            int tile = rem >> 1;          // kt*8 + nt
            int j = rem & 1;
            int kt = tile >> 3;
            int k0 = kt * 16 + cq * 2 + j * 8;
            int n = (tile & 7) * 8 + gq;
            const float* W = Ws[layer];
            float v0 = __ldg(W + k0 * 64 + n);
            float v1 = __ldg(W + (k0 + 1) * 64 + n);
            uint32_t hi, lo;
            split2(v0, v1, hi, lo);
            char* base = sm + layer * 16384 + tile * 256 + lane * 8 + j * 4;
            *reinterpret_cast<uint32_t*>(base) = hi;
            *reinterpret_cast<uint32_t*>(base + 8192) = lo;
        }
        if (tid < 64) ((float*)(sm + W22_OFF))[tid] = w22[tid];
    }
    __syncthreads();

    const float alpha = __ldg(alphap);
    const float beta = 1.f - alpha;

#pragma unroll 1
    for (int mt = 0; mt < 2; mt++) {
        const int base_row = blockIdx.x * BTPB + wid * 32 + mt * 16;
        uint32_t ahi[16], alo[16];

#pragma unroll
        for (int layer = 0; layer < 5; layer++) {
            float d[8][4];
#pragma unroll
            for (int nt = 0; nt < 8; nt++)
#pragma unroll
                for (int q = 0; q < 4; q++) d[nt][q] = 0.f;

            const char* wl = sm + layer * 16384;

#pragma unroll
            for (int kt = 0; kt < 4; kt++) {
                uint32_t Ah[4], Al[4];
                if (layer == 0) {
                    size_t p0 = (size_t)(kt * 8 + cq) * NMAX + base_row + gq;
                    Ah[0] = __ldcs(&g_feat[p0]);
                    Ah[1] = __ldcs(&g_feat[p0 + 8]);
                    Ah[2] = __ldcs(&g_feat[p0 + 4ull * NMAX]);
                    Ah[3] = __ldcs(&g_feat[p0 + 4ull * NMAX + 8]);
                    Al[0] = __ldcs(&g_feat[p0 + 32ull * NMAX]);
                    Al[1] = __ldcs(&g_feat[p0 + 32ull * NMAX + 8]);
                    Al[2] = __ldcs(&g_feat[p0 + 36ull * NMAX]);
                    Al[3] = __ldcs(&g_feat[p0 + 36ull * NMAX + 8]);
                } else {
#pragma unroll
                    for (int q = 0; q < 4; q++) { Ah[q] = ahi[kt * 4 + q]; Al[q] = alo[kt * 4 + q]; }
                }
#pragma unroll
                for (int nt = 0; nt < 8; nt++) {
                    const char* tb = wl + (kt * 8 + nt) * 256 + lane * 8;
                    uint2 bh = *reinterpret_cast<const uint2*>(tb);
                    uint2 bl = *reinterpret_cast<const uint2*>(tb + 8192);
                    mma16816(d[nt], Ah, bh.x, bh.y);
                    mma16816(d[nt], Ah, bl.x, bl.y);
                    mma16816(d[nt], Al, bh.x, bh.y);
                }
            }

            if (layer < 4) {
#pragma unroll
                for (int nt = 0; nt < 8; nt++) {
#pragma unroll
                    for (int q = 0; q < 4; q++) d[nt][q] = fmaxf(d[nt][q], 0.f);
                    if (layer == 2) {
                        size_t pw = (size_t)(nt * 4 + cq) * NMAX + base_row + gq;
                        uint32_t h0 = __ldcs(&g_feat[pw]);
                        uint32_t l0 = __ldcs(&g_feat[pw + 32ull * NMAX]);
                        uint32_t h8 = __ldcs(&g_feat[pw + 8]);
                        uint32_t l8 = __ldcs(&g_feat[pw + 32ull * NMAX + 8]);
                        d[nt][0] = d[nt][0] * alpha + beta * bf2sum(h0, l0, 0);
                        d[nt][1] = d[nt][1] * alpha + beta * bf2sum(h0, l0, 1);
                        d[nt][2] = d[nt][2] * alpha + beta * bf2sum(h8, l8, 0);
                        d[nt][3] = d[nt][3] * alpha + beta * bf2sum(h8, l8, 1);
                    }
                }
#pragma unroll
                for (int kt = 0; kt < 4; kt++) {
                    split2(d[2 * kt][0],     d[2 * kt][1],     ahi[kt * 4 + 0], alo[kt * 4 + 0]);
                    split2(d[2 * kt][2],     d[2 * kt][3],     ahi[kt * 4 + 1], alo[kt * 4 + 1]);
                    split2(d[2 * kt + 1][0], d[2 * kt + 1][1], ahi[kt * 4 + 2], alo[kt * 4 + 2]);
                    split2(d[2 * kt + 1][2], d[2 * kt + 1][3], ahi[kt * 4 + 3], alo[kt * 4 + 3]);
                }
            } else {
                float s0 = 0.f, s1 = 0.f;
#pragma unroll
                for (int nt = 0; nt < 8; nt++) {
                    float2 wv = *reinterpret_cast<const float2*>(sm + W22_OFF + nt * 32 + cq * 8);
                    s0 = fmaf(fmaxf(d[nt][0], 0.f), wv.x, s0);
                    s0 = fmaf(fmaxf(d[nt][1], 0.f), wv.y, s0);
                    s1 = fmaf(fmaxf(d[nt][2], 0.f), wv.x, s1);
                    s1 = fmaf(fmaxf(d[nt][3], 0.f), wv.y, s1);
                }
                s0 += __shfl_xor_sync(0xFFFFFFFF, s0, 1);
                s0 += __shfl_xor_sync(0xFFFFFFFF, s0, 2);
                s1 += __shfl_xor_sync(0xFFFFFFFF, s1, 1);
                s1 += __shfl_xor_sync(0xFFFFFFFF, s1, 2);
                if (cq == 0) {
                    int r0 = base_row + gq;
                    if (r0 < N) out[r0] = s0;
                    if (r0 + 8 < N) out[r0 + 8] = s1;
                }
            }
        }
    }
}

extern "C" void kernel_launch(void* const* d_in, const int* in_sizes, int n_in,
                              void* d_out, int out_size) {
    (void)in_sizes; (void)n_in;
    const float* x      = (const float*)d_in[0];
    const float* t      = (const float*)d_in[1];
    const float* tbl_s  = (const float*)d_in[2];
    const float* tbl_d  = (const float*)d_in[3];
    const float* w10    = (const float*)d_in[4];
    const float* w11    = (const float*)d_in[5];
    const float* w12    = (const float*)d_in[6];
    const float* w20    = (const float*)d_in[7];
    const float* w21    = (const float*)d_in[8];
    const float* w22    = (const float*)d_in[9];
    const float* alpha  = (const float*)d_in[10];
    float* out = (float*)d_out;

    int N = out_size;
    if (N <= 0) return;
    if (N > NMAX) N = NMAX;

    // RES[l] = floor(16 * b^l), identical double-precision expr as reference
    ResParams rp;
    double b = pow(2048.0 / 16.0, 1.0 / 15.0);
    for (int l = 0; l < NLEV; l++)
        rp.r[l] = (int)floor(16.0 * pow(b, (double)l));

    dim3 gridA((N + 255) / 256, 32);
    encode_kernel<<<gridA, 256>>>(x, t, tbl_s, tbl_d, N, rp);

    cudaFuncSetAttribute(mlp_kernel, cudaFuncAttributeMaxDynamicSharedMemorySize, BSMEM);
    int blocksB = (N + BTPB - 1) / BTPB;
    mlp_kernel<<<blocksB, BTPB, BSMEM>>>(w10, w11, w12, w20, w21, w22, alpha, out, N);
}

// round 8
// speedup vs baseline: 6.4286x; 1.2706x over previous
#include <cuda_runtime.h>
#include <cuda_bf16.h>
#include <math.h>
#include <stdint.h>

#define NLEV 16
#define TMASK ((1u << 19) - 1u)
#define PR1 2654435761u
#define PR2 805459861u
#define PR3 3674653429u
#define NMAX 2097152

// plane-major feature scratch: word c of point i at g_feat[c*NMAX + i]
// c in [0,32): bf16x2 hi words; c+32: lo words. 64 * 2M * 4B = 512 MB.
__device__ uint32_t g_feat[64ull * NMAX];
// time-fused dynamic tables: 16 levels x 512K float2 = 64 MB
__device__ float2 g_tbl_dyn[(size_t)NLEV << 19];

struct ResParams { int r[NLEV]; };

// ---------------- helpers ----------------
__device__ __forceinline__ void mma16816(float d[4], const uint32_t a[4], uint32_t b0, uint32_t b1) {
    asm volatile("mma.sync.aligned.m16n8k16.row.col.f32.bf16.bf16.f32 "
        "{%0,%1,%2,%3}, {%4,%5,%6,%7}, {%8,%9}, {%0,%1,%2,%3};"
        : "+f"(d[0]), "+f"(d[1]), "+f"(d[2]), "+f"(d[3])
        : "r"(a[0]), "r"(a[1]), "r"(a[2]), "r"(a[3]), "r"(b0), "r"(b1));
}

__device__ __forceinline__ void split2(float v0, float v1, uint32_t& hi, uint32_t& lo) {
    __nv_bfloat162 h, l;
    h.x = __float2bfloat16_rn(v0);
    h.y = __float2bfloat16_rn(v1);
    l.x = __float2bfloat16_rn(v0 - __bfloat162float(h.x));
    l.y = __float2bfloat16_rn(v1 - __bfloat162float(h.y));
    hi = *reinterpret_cast<uint32_t*>(&h);
    lo = *reinterpret_cast<uint32_t*>(&l);
}

__device__ __forceinline__ float bf2sum(uint32_t hi, uint32_t lo, int idx) {
    const __nv_bfloat162* h = reinterpret_cast<const __nv_bfloat162*>(&hi);
    const __nv_bfloat162* l = reinterpret_cast<const __nv_bfloat162*>(&lo);
    return idx == 0 ? (__bfloat162float(h->x) + __bfloat162float(l->x))
                    : (__bfloat162float(h->y) + __bfloat162float(l->y));
}

// elementwise float2 lerp: a + f*(b-a)
__device__ __forceinline__ float2 lerp2(float2 a, float2 b, float f) {
    float2 r;
    r.x = fmaf(f, b.x - a.x, a.x);
    r.y = fmaf(f, b.y - a.y, a.y);
    return r;
}

// ---------------- 3D hash-grid level encode (factored lerp tree) ----------------
__device__ __forceinline__ void enc3(const float2* __restrict__ tb, float x0, float x1, float x2,
                                     int R, float& o0, float& o1) {
    float fr = (float)R;
    float p0 = x0 * fr, p1 = x1 * fr, p2 = x2 * fr;
    float g0 = floorf(p0), g1 = floorf(p1), g2 = floorf(p2);
    float f0 = p0 - g0, f1 = p1 - g1, f2 = p2 - g2;
    unsigned i0 = (unsigned)(int)g0, i1 = (unsigned)(int)g1, i2 = (unsigned)(int)g2;
    unsigned hy0 = i1 * PR1, hy1 = hy0 + PR1;
    unsigned hz0 = i2 * PR2, hz1 = hz0 + PR2;
    unsigned hyz[4] = { hy0 ^ hz0, hy0 ^ hz1, hy1 ^ hz0, hy1 ^ hz1 };
    unsigned i0b = i0 + 1u;
    float2 v[8];
#pragma unroll
    for (int j = 0; j < 4; j++) {
        v[j]     = __ldg(tb + ((i0  ^ hyz[j]) & TMASK));
        v[4 + j] = __ldg(tb + ((i0b ^ hyz[j]) & TMASK));
    }
    float2 u0 = lerp2(v[0], v[4], f0);
    float2 u1 = lerp2(v[1], v[5], f0);
    float2 u2 = lerp2(v[2], v[6], f0);
    float2 u3 = lerp2(v[3], v[7], f0);
    float2 s0 = lerp2(u0, u2, f1);
    float2 s1 = lerp2(u1, u3, f1);
    float2 r  = lerp2(s0, s1, f2);
    o0 = r.x; o1 = r.y;
}

// ================= kernel P: fold scalar t into the dynamic tables =================
// T'[l][j] = (1-f3)*T[l][j ^ hw0] + f3*T[l][j ^ hw1]   (exact linear factorization)
// grid = (2048, 16), 256 threads. XOR-by-constant maps aligned 256-entry blocks to
// aligned 256-entry blocks -> fully coalesced reads.
__global__ void __launch_bounds__(256)
fuse_dyn_kernel(const float* __restrict__ tptr,
                const float* __restrict__ tbl_d, ResParams rp) {
    const int l = blockIdx.y;
    const unsigned j = blockIdx.x * 256 + threadIdx.x;
    const float tv = __ldg(tptr);
    const float p3 = tv * (float)rp.r[l];
    const float g3 = floorf(p3);
    const float f3 = p3 - g3;
    const unsigned i3 = (unsigned)(int)g3;
    const unsigned hw0 = (i3 * PR3) & TMASK;
    const unsigned hw1 = ((i3 + 1u) * PR3) & TMASK;
    const float2* tb = (const float2*)tbl_d + ((size_t)l << 19);
    float2 a = __ldg(tb + (j ^ hw0));
    float2 b = __ldg(tb + (j ^ hw1));
    g_tbl_dyn[((size_t)l << 19) + j] = lerp2(a, b, f3);
}

// ================= kernel A: level-parallel hash-grid encode =================
// grid = (ceil(N/256), 32): blockIdx.y = level slot (0-15 static, 16-31 time-fused dynamic)
__global__ void __launch_bounds__(256)
encode_kernel(const float* __restrict__ x,
              const float* __restrict__ tbl_s,
              int N, ResParams rp) {
    const int i = blockIdx.x * 256 + threadIdx.x;
    if (i >= N) return;
    const int lv = blockIdx.y;

    const float2* tb = (lv < 16)
        ? (const float2*)tbl_s + ((size_t)lv << 19)
        : (const float2*)g_tbl_dyn + ((size_t)(lv - 16) << 19);

    const float x0 = x[3 * i], x1 = x[3 * i + 1], x2 = x[3 * i + 2];
    float a0, a1;
    enc3(tb, x0, x1, x2, rp.r[lv & 15], a0, a1);

    uint32_t hi, lo;
    split2(a0, a1, hi, lo);
    // evict-first streaming stores: don't let the 512MB scratch evict the tables from L2
    __stcs(&g_feat[(size_t)lv * NMAX + i], hi);
    __stcs(&g_feat[(size_t)(32 + lv) * NMAX + i], lo);
}

// ================= kernel B: 5-layer MLP via HMMA =================
#define BTPB 256
#define BWARP 8
#define W22_OFF 81920
#define BSMEM (81920 + 256)

__global__ void __launch_bounds__(BTPB, 2)
mlp_kernel(const float* __restrict__ w10, const float* __restrict__ w11,
           const float* __restrict__ w12, const float* __restrict__ w20,
           const float* __restrict__ w21, const float* __restrict__ w22,
           const float* __restrict__ alphap,
           float* __restrict__ out, int N) {
    extern __shared__ char sm[];
    const int tid = threadIdx.x;
    const int wid = tid >> 5;
    const int lane = tid & 31;
    const int gq = lane >> 2;   // quad row 0..7
    const int cq = lane & 3;    // quad col 0..3

    // ---- stage weight fragments (B-fragment order, bf16 hi/lo) ----
    {
        const float* Ws[5] = { w10, w11, w12, w20, w21 };
#pragma unroll 1
        for (int g = wid; g < 320; g += BWARP) {
            int layer = g >> 6;
            int rem = g & 63;
            int tile = rem >> 1;          // kt*8 + nt
            int j = rem & 1;
            int kt = tile >> 3;
            int k0 = kt * 16 + cq * 2 + j * 8;
            int n = (tile & 7) * 8 + gq;
            const float* W = Ws[layer];
            float v0 = __ldg(W + k0 * 64 + n);
            float v1 = __ldg(W + (k0 + 1) * 64 + n);
            uint32_t hi, lo;
            split2(v0, v1, hi, lo);
            char* base = sm + layer * 16384 + tile * 256 + lane * 8 + j * 4;
            *reinterpret_cast<uint32_t*>(base) = hi;
            *reinterpret_cast<uint32_t*>(base + 8192) = lo;
        }
        if (tid < 64) ((float*)(sm + W22_OFF))[tid] = w22[tid];
    }
    __syncthreads();

    const float alpha = __ldg(alphap);
    const float beta = 1.f - alpha;

#pragma unroll 1
    for (int mt = 0; mt < 2; mt++) {
        const int base_row = blockIdx.x * BTPB + wid * 32 + mt * 16;
        uint32_t ahi[16], alo[16];

#pragma unroll
        for (int layer = 0; layer < 5; layer++) {
            float d[8][4];
#pragma unroll
            for (int nt = 0; nt < 8; nt++)
#pragma unroll
                for (int q = 0; q < 4; q++) d[nt][q] = 0.f;

            const char* wl = sm + layer * 16384;

#pragma unroll
            for (int kt = 0; kt < 4; kt++) {
                uint32_t Ah[4], Al[4];
                if (layer == 0) {
                    size_t p0 = (size_t)(kt * 8 + cq) * NMAX + base_row + gq;
                    Ah[0] = __ldcs(&g_feat[p0]);
                    Ah[1] = __ldcs(&g_feat[p0 + 8]);
                    Ah[2] = __ldcs(&g_feat[p0 + 4ull * NMAX]);
                    Ah[3] = __ldcs(&g_feat[p0 + 4ull * NMAX + 8]);
                    Al[0] = __ldcs(&g_feat[p0 + 32ull * NMAX]);
                    Al[1] = __ldcs(&g_feat[p0 + 32ull * NMAX + 8]);
                    Al[2] = __ldcs(&g_feat[p0 + 36ull * NMAX]);
                    Al[3] = __ldcs(&g_feat[p0 + 36ull * NMAX + 8]);
                } else {
#pragma unroll
                    for (int q = 0; q < 4; q++) { Ah[q] = ahi[kt * 4 + q]; Al[q] = alo[kt * 4 + q]; }
                }
#pragma unroll
                for (int nt = 0; nt < 8; nt++) {
                    const char* tb = wl + (kt * 8 + nt) * 256 + lane * 8;
                    uint2 bh = *reinterpret_cast<const uint2*>(tb);
                    uint2 bl = *reinterpret_cast<const uint2*>(tb + 8192);
                    mma16816(d[nt], Ah, bh.x, bh.y);
                    mma16816(d[nt], Ah, bl.x, bl.y);
                    mma16816(d[nt], Al, bh.x, bh.y);
                }
            }

            if (layer < 4) {
#pragma unroll
                for (int nt = 0; nt < 8; nt++) {
#pragma unroll
                    for (int q = 0; q < 4; q++) d[nt][q] = fmaxf(d[nt][q], 0.f);
                    if (layer == 2) {
                        size_t pw = (size_t)(nt * 4 + cq) * NMAX + base_row + gq;
                        uint32_t h0 = __ldcs(&g_feat[pw]);
                        uint32_t l0 = __ldcs(&g_feat[pw + 32ull * NMAX]);
                        uint32_t h8 = __ldcs(&g_feat[pw + 8]);
                        uint32_t l8 = __ldcs(&g_feat[pw + 32ull * NMAX + 8]);
                        d[nt][0] = d[nt][0] * alpha + beta * bf2sum(h0, l0, 0);
                        d[nt][1] = d[nt][1] * alpha + beta * bf2sum(h0, l0, 1);
                        d[nt][2] = d[nt][2] * alpha + beta * bf2sum(h8, l8, 0);
                        d[nt][3] = d[nt][3] * alpha + beta * bf2sum(h8, l8, 1);
                    }
                }
#pragma unroll
                for (int kt = 0; kt < 4; kt++) {
                    split2(d[2 * kt][0],     d[2 * kt][1],     ahi[kt * 4 + 0], alo[kt * 4 + 0]);
                    split2(d[2 * kt][2],     d[2 * kt][3],     ahi[kt * 4 + 1], alo[kt * 4 + 1]);
                    split2(d[2 * kt + 1][0], d[2 * kt + 1][1], ahi[kt * 4 + 2], alo[kt * 4 + 2]);
                    split2(d[2 * kt + 1][2], d[2 * kt + 1][3], ahi[kt * 4 + 3], alo[kt * 4 + 3]);
                }
            } else {
                float s0 = 0.f, s1 = 0.f;
#pragma unroll
                for (int nt = 0; nt < 8; nt++) {
                    float2 wv = *reinterpret_cast<const float2*>(sm + W22_OFF + nt * 32 + cq * 8);
                    s0 = fmaf(fmaxf(d[nt][0], 0.f), wv.x, s0);
                    s0 = fmaf(fmaxf(d[nt][1], 0.f), wv.y, s0);
                    s1 = fmaf(fmaxf(d[nt][2], 0.f), wv.x, s1);
                    s1 = fmaf(fmaxf(d[nt][3], 0.f), wv.y, s1);
                }
                s0 += __shfl_xor_sync(0xFFFFFFFF, s0, 1);
                s0 += __shfl_xor_sync(0xFFFFFFFF, s0, 2);
                s1 += __shfl_xor_sync(0xFFFFFFFF, s1, 1);
                s1 += __shfl_xor_sync(0xFFFFFFFF, s1, 2);
                if (cq == 0) {
                    int r0 = base_row + gq;
                    if (r0 < N) out[r0] = s0;
                    if (r0 + 8 < N) out[r0 + 8] = s1;
                }
            }
        }
    }
}

extern "C" void kernel_launch(void* const* d_in, const int* in_sizes, int n_in,
                              void* d_out, int out_size) {
    (void)in_sizes; (void)n_in;
    const float* x      = (const float*)d_in[0];
    const float* t      = (const float*)d_in[1];
    const float* tbl_s  = (const float*)d_in[2];
    const float* tbl_d  = (const float*)d_in[3];
    const float* w10    = (const float*)d_in[4];
    const float* w11    = (const float*)d_in[5];
    const float* w12    = (const float*)d_in[6];
    const float* w20    = (const float*)d_in[7];
    const float* w21    = (const float*)d_in[8];
    const float* w22    = (const float*)d_in[9];
    const float* alpha  = (const float*)d_in[10];
    float* out = (float*)d_out;

    int N = out_size;
    if (N <= 0) return;
    if (N > NMAX) N = NMAX;

    // RES[l] = floor(16 * b^l), identical double-precision expr as reference
    ResParams rp;
    double b = pow(2048.0 / 16.0, 1.0 / 15.0);
    for (int l = 0; l < NLEV; l++)
        rp.r[l] = (int)floor(16.0 * pow(b, (double)l));

    // fold scalar t into dynamic tables (4D -> 3D)
    dim3 gridP(2048, 16);
    fuse_dyn_kernel<<<gridP, 256>>>(t, tbl_d, rp);

    dim3 gridA((N + 255) / 256, 32);
    encode_kernel<<<gridA, 256>>>(x, tbl_s, N, rp);

    cudaFuncSetAttribute(mlp_kernel, cudaFuncAttributeMaxDynamicSharedMemorySize, BSMEM);
    int blocksB = (N + BTPB - 1) / BTPB;
    mlp_kernel<<<blocksB, BTPB, BSMEM>>>(w10, w11, w12, w20, w21, w22, alpha, out, N);
}